// round 9
// baseline (speedup 1.0000x reference)
#include <cuda_runtime.h>
#include <cuda_bf16.h>
#include <cstdint>
#include <math.h>

#define Bn 32
#define Tn 2048
#define Dn 512
#define ZB 32
#define SPLIT 32
#define SEG 8
#define NIT (Tn / 32)

#define NT 16
#define NTILE (NT * (NT + 1) / 2)   // 136 lower cov tiles
#define CSZ 8                        // cluster size

// ---------------- static scratch ----------------
__device__ float g_pmean[SEG][Bn][Dn];
__device__ float g_bmean[Bn][Dn];
__device__ float g_gmean[Dn];
__device__ float g_zT[Dn * ZB];                 // z transposed [e][s]
__device__ __nv_bfloat16 g_xcb[(size_t)Bn * Tn * Dn];
__device__ float g_Gpart[SPLIT][Dn * Dn];
__device__ float g_C[Dn * Dn];                  // L (lower tiles valid)

__device__ __forceinline__ uint32_t smem_u32(const void* p) {
    return (uint32_t)__cvta_generic_to_shared(p);
}

// cluster-wide sync with global-memory visibility (fence scope>=cluster -> L1 inval)
#define CSYNC() asm volatile( \
    "fence.acq_rel.cluster;\n\t" \
    "barrier.cluster.arrive.aligned;\n\t" \
    "barrier.cluster.wait.aligned;" ::: "memory")

// ---------------- 1) fused partial means + bf16 convert ---------------------
__global__ void conv_mean(const float* __restrict__ x) {
    int b   = blockIdx.y;
    int seg = blockIdx.z;
    int d   = blockIdx.x * 128 + threadIdx.x;
    size_t base = ((size_t)b * Tn + (size_t)seg * (Tn / SEG)) * Dn + d;
    float s = 0.f;
#pragma unroll 4
    for (int t = 0; t < Tn / SEG; t++) {
        float f = x[base + (size_t)t * Dn];
        s += f;
        g_xcb[base + (size_t)t * Dn] = __float2bfloat16_rn(f);
    }
    g_pmean[seg][b][d] = s;
}

// ---------------- 2) tensor-core Gram (validated, unchanged) ----------------
__global__ void __launch_bounds__(256) gram_mma(const __nv_bfloat16* __restrict__ xb) {
    if (blockIdx.y > blockIdx.x) return;
    int dtile = blockIdx.x * 128;
    int etile = blockIdx.y * 128;
    int bz    = blockIdx.z;

    __shared__ __nv_bfloat16 As[2][32][128];
    __shared__ __nv_bfloat16 Bs[2][32][128];

    int tid  = threadIdx.x;
    int lane = tid & 31;
    int warp = tid >> 5;
    int m0 = (warp >> 2) * 64;
    int n0 = (warp & 3) * 32;

    const __nv_bfloat16* xbase = xb + (size_t)bz * Tn * Dn;

    float acc[4][4][4];
#pragma unroll
    for (int a = 0; a < 4; a++)
#pragma unroll
        for (int b = 0; b < 4; b++)
#pragma unroll
            for (int c = 0; c < 4; c++) acc[a][b][c] = 0.f;

    auto issue = [&](int it, int stg) {
#pragma unroll
        for (int rep = 0; rep < 2; rep++) {
            int l    = tid + rep * 256;
            int row  = l >> 4;
            int ch   = l & 15;
            int chs  = ch ^ (row & 7);
            const __nv_bfloat16* gA = xbase + (size_t)(it * 32 + row) * Dn + dtile + ch * 8;
            const __nv_bfloat16* gB = xbase + (size_t)(it * 32 + row) * Dn + etile + ch * 8;
            uint32_t sA = smem_u32(&As[stg][row][chs * 8]);
            uint32_t sB = smem_u32(&Bs[stg][row][chs * 8]);
            asm volatile("cp.async.cg.shared.global [%0], [%1], 16;" :: "r"(sA), "l"(gA));
            asm volatile("cp.async.cg.shared.global [%0], [%1], 16;" :: "r"(sB), "l"(gB));
        }
    };

    issue(0, 0);
    asm volatile("cp.async.commit_group;");

    for (int it = 0; it < NIT; it++) {
        if (it + 1 < NIT) {
            issue(it + 1, (it + 1) & 1);
            asm volatile("cp.async.commit_group;");
            asm volatile("cp.async.wait_group 1;");
        } else {
            asm volatile("cp.async.wait_group 0;");
        }
        __syncthreads();
        int stg = it & 1;

#pragma unroll
        for (int ks = 0; ks < 2; ks++) {
            uint32_t a[4][4];
            uint32_t bfr[2][4];
#pragma unroll
            for (int mi = 0; mi < 4; mi++) {
                int krow = ks * 16 + (lane & 7) + ((lane & 16) ? 8 : 0);
                int ch   = (m0 >> 3) + mi * 2 + ((lane >> 3) & 1);
                int chs  = ch ^ (krow & 7);
                uint32_t addr = smem_u32(&As[stg][krow][chs * 8]);
                asm volatile("ldmatrix.sync.aligned.m8n8.x4.trans.shared.b16 {%0,%1,%2,%3}, [%4];"
                             : "=r"(a[mi][0]), "=r"(a[mi][1]), "=r"(a[mi][2]), "=r"(a[mi][3])
                             : "r"(addr));
            }
#pragma unroll
            for (int pb = 0; pb < 2; pb++) {
                int krow = ks * 16 + (lane & 7) + ((lane & 8) ? 8 : 0);
                int ch   = (n0 >> 3) + pb * 2 + ((lane >> 4) & 1);
                int chs  = ch ^ (krow & 7);
                uint32_t addr = smem_u32(&Bs[stg][krow][chs * 8]);
                asm volatile("ldmatrix.sync.aligned.m8n8.x4.trans.shared.b16 {%0,%1,%2,%3}, [%4];"
                             : "=r"(bfr[pb][0]), "=r"(bfr[pb][1]), "=r"(bfr[pb][2]), "=r"(bfr[pb][3])
                             : "r"(addr));
            }
#pragma unroll
            for (int mi = 0; mi < 4; mi++)
#pragma unroll
                for (int nb = 0; nb < 4; nb++) {
                    uint32_t b0 = bfr[nb >> 1][(nb & 1) * 2];
                    uint32_t b1 = bfr[nb >> 1][(nb & 1) * 2 + 1];
                    asm volatile(
                        "mma.sync.aligned.m16n8k16.row.col.f32.bf16.bf16.f32 "
                        "{%0,%1,%2,%3}, {%4,%5,%6,%7}, {%8,%9}, {%0,%1,%2,%3};"
                        : "+f"(acc[mi][nb][0]), "+f"(acc[mi][nb][1]),
                          "+f"(acc[mi][nb][2]), "+f"(acc[mi][nb][3])
                        : "r"(a[mi][0]), "r"(a[mi][1]), "r"(a[mi][2]), "r"(a[mi][3]),
                          "r"(b0), "r"(b1));
                }
        }
        __syncthreads();
    }

    float* gp = g_Gpart[bz];
    int g  = lane >> 2;
    int tg = lane & 3;
#pragma unroll
    for (int mi = 0; mi < 4; mi++)
#pragma unroll
        for (int nb = 0; nb < 4; nb++) {
            int row = dtile + m0 + mi * 16 + g;
            int col = etile + n0 + nb * 8 + tg * 2;
            *(float2*)&gp[(size_t)row * Dn + col]       = make_float2(acc[mi][nb][0], acc[mi][nb][1]);
            *(float2*)&gp[(size_t)(row + 8) * Dn + col] = make_float2(acc[mi][nb][2], acc[mi][nb][3]);
        }
}

// ---------------- warp-shuffle 32x32 Cholesky factor (stride-33 smem) -------
__device__ __forceinline__ void factor32_warp(float* s, int lane) {
    float a[32];
#pragma unroll
    for (int i = 0; i < 32; i++) a[i] = (i >= lane) ? s[i * 33 + lane] : 0.f;
#pragma unroll
    for (int j = 0; j < 32; j++) {
        float pivot = __shfl_sync(0xffffffffu, a[j], j);
        float rinv  = 1.0f / sqrtf(pivot);
        float lej = 0.f;
#pragma unroll
        for (int i = 0; i < 32; i++) {
            float lij = __shfl_sync(0xffffffffu, a[i], j) * rinv;
            if (i == lane) lej = lij;
            if (lane == j) a[i] = lij;
            else if (lane > j && i >= lane) a[i] -= lij * lej;
        }
    }
#pragma unroll
    for (int i = 0; i < 32; i++)
        if (i >= lane) s[i * 33 + lane] = a[i];
}

// ---------------- 3) cluster kernel: means + reduce + Cholesky + output -----
__global__ void __cluster_dims__(CSZ, 1, 1) __launch_bounds__(256)
cluster_chol(const float* __restrict__ z, float* __restrict__ out) {
    __shared__ float Dg[32 * 33];
    __shared__ float Pi[32 * 33];
    __shared__ float Pk[32 * 33];

    unsigned crank;
    asm("mov.u32 %0, %%cluster_ctarank;" : "=r"(crank));
    int tid  = threadIdx.x;
    int gtid = crank * 256 + tid;          // 0..2047

    // ---- A1: bmean/gmean for d-slice [crank*64, +64); transpose z ----
    if (tid < 64) {
        int d = crank * 64 + tid;
        float gsum = 0.f;
#pragma unroll
        for (int b = 0; b < Bn; b++) {
            float s = 0.f;
#pragma unroll
            for (int g = 0; g < SEG; g++) s += g_pmean[g][b][d];
            float bm = s * (1.0f / (float)Tn);
            g_bmean[b][d] = bm;
            gsum += bm;
        }
        g_gmean[d] = gsum * (1.0f / (float)Bn);
    }
    for (int idx = gtid; idx < ZB * Dn; idx += CSZ * 256) {
        int s = idx >> 9, e = idx & 511;
        g_zT[e * ZB + s] = z[idx];
    }
    CSYNC();

    // ---- A2: covariance lower tiles (round-robin over 136) ----
    {
        const float inv = 1.0f / ((float)(Tn - 1) * (float)Bn);
        int r  = tid >> 3;
        int cb = (tid & 7) * 4;
        for (int t = crank; t < NTILE; t += CSZ) {
            int ti = 0;
            while ((ti + 1) * (ti + 2) / 2 <= t) ti++;
            int tj = t - ti * (ti + 1) / 2;
            for (int l = tid; l < Bn * 32; l += 256) {
                int b = l >> 5, rr = l & 31;
                Pi[b * 33 + rr] = g_bmean[b][ti * 32 + rr];
                Pk[b * 33 + rr] = g_bmean[b][tj * 32 + rr];
            }
            __syncthreads();
            float4 gs = make_float4(0.f, 0.f, 0.f, 0.f);
            size_t gidx = (size_t)(ti * 32 + r) * Dn + tj * 32 + cb;
#pragma unroll
            for (int g = 0; g < SPLIT; g++) {
                float4 v = *(const float4*)&g_Gpart[g][gidx];
                gs.x += v.x; gs.y += v.y; gs.z += v.z; gs.w += v.w;
            }
            float mk[4] = {0.f, 0.f, 0.f, 0.f};
#pragma unroll
            for (int b = 0; b < Bn; b++) {
                float pir = Pi[b * 33 + r];
#pragma unroll
                for (int c = 0; c < 4; c++) mk[c] += pir * Pk[b * 33 + cb + c];
            }
            float4 res;
            res.x = (gs.x - (float)Tn * mk[0]) * inv;
            res.y = (gs.y - (float)Tn * mk[1]) * inv;
            res.z = (gs.z - (float)Tn * mk[2]) * inv;
            res.w = (gs.w - (float)Tn * mk[3]) * inv;
            *(float4*)&g_C[gidx] = res;
            __syncthreads();
        }
    }
    CSYNC();

    // ---- diag 0 factor (CTA 0) ----
    if (crank == 0) {
        for (int l = tid; l < 1024; l += 256)
            Dg[(l >> 5) * 33 + (l & 31)] = g_C[(size_t)(l >> 5) * Dn + (l & 31)];
        __syncthreads();
        if (tid < 32) factor32_warp(Dg, tid);
        __syncthreads();
        for (int l = tid; l < 1024; l += 256) {
            int i = l >> 5, k = l & 31;
            if (k <= i) g_C[(size_t)i * Dn + k] = Dg[i * 33 + k];
        }
    }
    CSYNC();

    // ---- panels ----
    for (int p = 0; p < 15; p++) {
        int j0 = p * 32;
        int r0 = j0 + 32;
        int n  = Dn - r0;

        // TRSM: one row per cluster thread
        for (int l = tid; l < 1024; l += 256)
            Dg[(l >> 5) * 33 + (l & 31)] = g_C[(size_t)(j0 + (l >> 5)) * Dn + j0 + (l & 31)];
        __syncthreads();
        if (gtid < n) {
            int row = r0 + gtid;
            float t[32];
#pragma unroll
            for (int q = 0; q < 8; q++)
                *(float4*)&t[q * 4] = *(const float4*)&g_C[(size_t)row * Dn + j0 + q * 4];
#pragma unroll
            for (int j = 0; j < 32; j++) {
                float v = t[j];
                for (int k = 0; k < j; k++) v -= t[k] * Dg[j * 33 + k];
                t[j] = v / Dg[j * 33 + j];
            }
#pragma unroll
            for (int q = 0; q < 8; q++)
                *(float4*)&g_C[(size_t)row * Dn + j0 + q * 4] = *(const float4*)&t[q * 4];
        }
        CSYNC();

        // SYRK trailing tiles (lower), round-robin; tile 0 = next diag (factor)
        int nt = n / 32;
        int ntile = nt * (nt + 1) / 2;
        int r  = tid >> 3;
        int cb = (tid & 7) * 4;
        for (int t = crank; t < ntile; t += CSZ) {
            int ti = 0;
            while ((ti + 1) * (ti + 2) / 2 <= t) ti++;
            int tj = t - ti * (ti + 1) / 2;
            int i0 = r0 + ti * 32, k0 = r0 + tj * 32;

            for (int l = tid; l < 1024; l += 256) {
                int rr = l >> 5, cc = l & 31;
                Pi[rr * 33 + cc] = g_C[(size_t)(i0 + rr) * Dn + j0 + cc];
                Pk[rr * 33 + cc] = g_C[(size_t)(k0 + rr) * Dn + j0 + cc];
            }
            __syncthreads();

            float acc[4] = {0.f, 0.f, 0.f, 0.f};
#pragma unroll 8
            for (int m = 0; m < 32; m++) {
                float a = Pi[r * 33 + m];
#pragma unroll
                for (int c = 0; c < 4; c++) acc[c] += a * Pk[(cb + c) * 33 + m];
            }

            if (t == 0) {
                // next panel's diagonal: update + factor + write lower
                float val[4];
#pragma unroll
                for (int c = 0; c < 4; c++)
                    val[c] = g_C[(size_t)(i0 + r) * Dn + k0 + cb + c] - acc[c];
#pragma unroll
                for (int c = 0; c < 4; c++) Dg[r * 33 + cb + c] = val[c];
                __syncthreads();
                if (tid < 32) factor32_warp(Dg, tid);
                __syncthreads();
                for (int l = tid; l < 1024; l += 256) {
                    int ii = l >> 5, kk = l & 31;
                    if (kk <= ii) g_C[(size_t)(i0 + ii) * Dn + k0 + kk] = Dg[ii * 33 + kk];
                }
            } else if (ti == tj) {
#pragma unroll
                for (int c = 0; c < 4; c++)
                    if (cb + c <= r)
                        g_C[(size_t)(i0 + r) * Dn + k0 + cb + c] -= acc[c];
            } else {
#pragma unroll
                for (int c = 0; c < 4; c++)
                    g_C[(size_t)(i0 + r) * Dn + k0 + cb + c] -= acc[c];
            }
            __syncthreads();
        }
        CSYNC();
    }

    // ---- output: warp per d, lane = sample s (zT coalesced, Crow broadcast)
    {
        int lane = tid & 31;
        int gw   = crank * 8 + (tid >> 5);      // 64 warps
        for (int d = gw; d < Dn; d += CSZ * 8) {
            const float* Crow = g_C + (size_t)d * Dn;
            float acc = g_gmean[d];
            for (int e = 0; e <= d; e++)
                acc += g_zT[e * ZB + lane] * Crow[e];
            out[(size_t)lane * Dn + d] = acc;
        }
    }
}

// ---------------- launch -----------------------------------------------------
extern "C" void kernel_launch(void* const* d_in, const int* in_sizes, int n_in,
                              void* d_out, int out_size) {
    const float* x = (const float*)d_in[0];
    const float* z = (const float*)d_in[1];
    if (in_sizes[0] != Bn * Tn * Dn) { x = (const float*)d_in[1]; z = (const float*)d_in[0]; }
    float* out = (float*)d_out;

    conv_mean<<<dim3(4, Bn, SEG), 128>>>(x);

    __nv_bfloat16* xcb;
    cudaGetSymbolAddress((void**)&xcb, g_xcb);
    gram_mma<<<dim3(4, 4, SPLIT), 256>>>(xcb);

    cluster_chol<<<CSZ, 256>>>(z, out);
}

// round 11
// speedup vs baseline: 1.5776x; 1.5776x over previous
#include <cuda_runtime.h>
#include <cuda_bf16.h>
#include <cstdint>
#include <math.h>

#define Bn 32
#define Tn 2048
#define Dn 512
#define ZB 32
#define SPLIT 32
#define SEG 8
#define NIT (Tn / 32)

#define NT 16
#define NTILE (NT * (NT + 1) / 2)   // 136 lower cov tiles
#define NBLK 120
#define NTHR 256

// ---------------- static scratch ----------------
__device__ float g_pmean[SEG][Bn][Dn];
__device__ float g_zT[Dn * ZB];                 // z transposed [e][s]
__device__ __nv_bfloat16 g_xcb[(size_t)Bn * Tn * Dn];
__device__ float g_Gpart[SPLIT][Dn * Dn];
__device__ float g_C[Dn * Dn];                  // raw updated covariance (lower tiles)
__device__ float g_L[Dn * Dn];                  // Cholesky factor L (lower)
__device__ unsigned g_barrier;

__device__ __forceinline__ uint32_t smem_u32(const void* p) {
    return (uint32_t)__cvta_generic_to_shared(p);
}

// grid barrier: release-add, relaxed spin, single acquire fence
__device__ __forceinline__ void gbar(unsigned* phase) {
    __syncthreads();
    if (threadIdx.x == 0) {
        unsigned target = (++(*phase)) * NBLK;
        asm volatile("red.release.gpu.add.u32 [%0], 1;" :: "l"(&g_barrier) : "memory");
        unsigned v;
        do {
            asm volatile("ld.relaxed.gpu.u32 %0, [%1];" : "=r"(v) : "l"(&g_barrier) : "memory");
        } while (v < target);
        asm volatile("fence.acq_rel.gpu;" ::: "memory");
    }
    __syncthreads();
}

// ---------------- 1) fused partial means + bf16 convert ---------------------
__global__ void conv_mean(const float* __restrict__ x) {
    int b   = blockIdx.y;
    int seg = blockIdx.z;
    int d   = blockIdx.x * 128 + threadIdx.x;
    if (blockIdx.x == 0 && b == 0 && seg == 0 && threadIdx.x == 0) g_barrier = 0u;
    size_t base = ((size_t)b * Tn + (size_t)seg * (Tn / SEG)) * Dn + d;
    float s = 0.f;
#pragma unroll 4
    for (int t = 0; t < Tn / SEG; t++) {
        float f = x[base + (size_t)t * Dn];
        s += f;
        g_xcb[base + (size_t)t * Dn] = __float2bfloat16_rn(f);
    }
    g_pmean[seg][b][d] = s;
}

// ---------------- 2) tensor-core Gram (validated, unchanged) ----------------
__global__ void __launch_bounds__(256) gram_mma(const __nv_bfloat16* __restrict__ xb) {
    if (blockIdx.y > blockIdx.x) return;
    int dtile = blockIdx.x * 128;
    int etile = blockIdx.y * 128;
    int bz    = blockIdx.z;

    __shared__ __nv_bfloat16 As[2][32][128];
    __shared__ __nv_bfloat16 Bs[2][32][128];

    int tid  = threadIdx.x;
    int lane = tid & 31;
    int warp = tid >> 5;
    int m0 = (warp >> 2) * 64;
    int n0 = (warp & 3) * 32;

    const __nv_bfloat16* xbase = xb + (size_t)bz * Tn * Dn;

    float acc[4][4][4];
#pragma unroll
    for (int a = 0; a < 4; a++)
#pragma unroll
        for (int b = 0; b < 4; b++)
#pragma unroll
            for (int c = 0; c < 4; c++) acc[a][b][c] = 0.f;

    auto issue = [&](int it, int stg) {
#pragma unroll
        for (int rep = 0; rep < 2; rep++) {
            int l    = tid + rep * 256;
            int row  = l >> 4;
            int ch   = l & 15;
            int chs  = ch ^ (row & 7);
            const __nv_bfloat16* gA = xbase + (size_t)(it * 32 + row) * Dn + dtile + ch * 8;
            const __nv_bfloat16* gB = xbase + (size_t)(it * 32 + row) * Dn + etile + ch * 8;
            uint32_t sA = smem_u32(&As[stg][row][chs * 8]);
            uint32_t sB = smem_u32(&Bs[stg][row][chs * 8]);
            asm volatile("cp.async.cg.shared.global [%0], [%1], 16;" :: "r"(sA), "l"(gA));
            asm volatile("cp.async.cg.shared.global [%0], [%1], 16;" :: "r"(sB), "l"(gB));
        }
    };

    issue(0, 0);
    asm volatile("cp.async.commit_group;");

    for (int it = 0; it < NIT; it++) {
        if (it + 1 < NIT) {
            issue(it + 1, (it + 1) & 1);
            asm volatile("cp.async.commit_group;");
            asm volatile("cp.async.wait_group 1;");
        } else {
            asm volatile("cp.async.wait_group 0;");
        }
        __syncthreads();
        int stg = it & 1;

#pragma unroll
        for (int ks = 0; ks < 2; ks++) {
            uint32_t a[4][4];
            uint32_t bfr[2][4];
#pragma unroll
            for (int mi = 0; mi < 4; mi++) {
                int krow = ks * 16 + (lane & 7) + ((lane & 16) ? 8 : 0);
                int ch   = (m0 >> 3) + mi * 2 + ((lane >> 3) & 1);
                int chs  = ch ^ (krow & 7);
                uint32_t addr = smem_u32(&As[stg][krow][chs * 8]);
                asm volatile("ldmatrix.sync.aligned.m8n8.x4.trans.shared.b16 {%0,%1,%2,%3}, [%4];"
                             : "=r"(a[mi][0]), "=r"(a[mi][1]), "=r"(a[mi][2]), "=r"(a[mi][3])
                             : "r"(addr));
            }
#pragma unroll
            for (int pb = 0; pb < 2; pb++) {
                int krow = ks * 16 + (lane & 7) + ((lane & 8) ? 8 : 0);
                int ch   = (n0 >> 3) + pb * 2 + ((lane >> 4) & 1);
                int chs  = ch ^ (krow & 7);
                uint32_t addr = smem_u32(&Bs[stg][krow][chs * 8]);
                asm volatile("ldmatrix.sync.aligned.m8n8.x4.trans.shared.b16 {%0,%1,%2,%3}, [%4];"
                             : "=r"(bfr[pb][0]), "=r"(bfr[pb][1]), "=r"(bfr[pb][2]), "=r"(bfr[pb][3])
                             : "r"(addr));
            }
#pragma unroll
            for (int mi = 0; mi < 4; mi++)
#pragma unroll
                for (int nb = 0; nb < 4; nb++) {
                    uint32_t b0 = bfr[nb >> 1][(nb & 1) * 2];
                    uint32_t b1 = bfr[nb >> 1][(nb & 1) * 2 + 1];
                    asm volatile(
                        "mma.sync.aligned.m16n8k16.row.col.f32.bf16.bf16.f32 "
                        "{%0,%1,%2,%3}, {%4,%5,%6,%7}, {%8,%9}, {%0,%1,%2,%3};"
                        : "+f"(acc[mi][nb][0]), "+f"(acc[mi][nb][1]),
                          "+f"(acc[mi][nb][2]), "+f"(acc[mi][nb][3])
                        : "r"(a[mi][0]), "r"(a[mi][1]), "r"(a[mi][2]), "r"(a[mi][3]),
                          "r"(b0), "r"(b1));
                }
        }
        __syncthreads();
    }

    float* gp = g_Gpart[bz];
    int g  = lane >> 2;
    int tg = lane & 3;
#pragma unroll
    for (int mi = 0; mi < 4; mi++)
#pragma unroll
        for (int nb = 0; nb < 4; nb++) {
            int row = dtile + m0 + mi * 16 + g;
            int col = etile + n0 + nb * 8 + tg * 2;
            *(float2*)&gp[(size_t)row * Dn + col]       = make_float2(acc[mi][nb][0], acc[mi][nb][1]);
            *(float2*)&gp[(size_t)(row + 8) * Dn + col] = make_float2(acc[mi][nb][2], acc[mi][nb][3]);
        }
}

// ---------------- warp-shuffle 32x32 Cholesky factor (stride-33 smem) -------
__device__ __forceinline__ void factor32_warp(float* s, int lane) {
    float a[32];
#pragma unroll
    for (int i = 0; i < 32; i++) a[i] = (i >= lane) ? s[i * 33 + lane] : 0.f;
#pragma unroll
    for (int j = 0; j < 32; j++) {
        float pivot = __shfl_sync(0xffffffffu, a[j], j);
        float rinv  = 1.0f / sqrtf(pivot);
        float lej = 0.f;
#pragma unroll
        for (int i = 0; i < 32; i++) {
            float lij = __shfl_sync(0xffffffffu, a[i], j) * rinv;
            if (i == lane) lej = lij;
            if (lane == j) a[i] = lij;
            else if (lane > j && i >= lane) a[i] -= lij * lej;
        }
    }
#pragma unroll
    for (int i = 0; i < 32; i++)
        if (i >= lane) s[i * 33 + lane] = a[i];
}

// ---------------- 3) persistent chol: 1 barrier per panel -------------------
__global__ void __launch_bounds__(NTHR) chol_fast(const float* __restrict__ z,
                                                  float* __restrict__ out) {
    __shared__ float Pi[32 * 33];
    __shared__ float Pk[32 * 33];
    __shared__ float Dg[32 * 33];
    __shared__ float sDinv[32];

    unsigned phase = 0;
    int bid = blockIdx.x, tid = threadIdx.x;

    // ---- phase A: z transpose + cov lower tiles (bmean from g_pmean) ----
    for (int idx = bid * NTHR + tid; idx < ZB * Dn; idx += NBLK * NTHR) {
        int s = idx >> 9, e = idx & 511;
        g_zT[e * ZB + s] = z[idx];
    }
    {
        const float inv   = 1.0f / ((float)(Tn - 1) * (float)Bn);
        const float tninv = 1.0f / (float)Tn;
        int r  = tid >> 3;
        int cb = (tid & 7) * 4;
        for (int t = bid; t < NTILE; t += NBLK) {
            int ti = 0;
            while ((ti + 1) * (ti + 2) / 2 <= t) ti++;
            int tj = t - ti * (ti + 1) / 2;
            __syncthreads();
            for (int l = tid; l < Bn * 32; l += NTHR) {
                int b = l >> 5, rr = l & 31;
                float s1 = 0.f, s2 = 0.f;
#pragma unroll
                for (int sg = 0; sg < SEG; sg++) {
                    s1 += g_pmean[sg][b][ti * 32 + rr];
                    s2 += g_pmean[sg][b][tj * 32 + rr];
                }
                Pi[b * 33 + rr] = s1 * tninv;
                Pk[b * 33 + rr] = s2 * tninv;
            }
            __syncthreads();
            float4 gs = make_float4(0.f, 0.f, 0.f, 0.f);
            size_t gidx = (size_t)(ti * 32 + r) * Dn + tj * 32 + cb;
#pragma unroll
            for (int g = 0; g < SPLIT; g++) {
                float4 v = *(const float4*)&g_Gpart[g][gidx];
                gs.x += v.x; gs.y += v.y; gs.z += v.z; gs.w += v.w;
            }
            float mk[4] = {0.f, 0.f, 0.f, 0.f};
#pragma unroll
            for (int b = 0; b < Bn; b++) {
                float pir = Pi[b * 33 + r];
#pragma unroll
                for (int c = 0; c < 4; c++) mk[c] += pir * Pk[b * 33 + cb + c];
            }
            float4 res;
            res.x = (gs.x - (float)Tn * mk[0]) * inv;
            res.y = (gs.y - (float)Tn * mk[1]) * inv;
            res.z = (gs.z - (float)Tn * mk[2]) * inv;
            res.w = (gs.w - (float)Tn * mk[3]) * inv;
            *(float4*)&g_C[gidx] = res;
        }
    }
    gbar(&phase);

    // ---- panels: each block factors diag locally; one barrier per panel ----
    for (int p = 0; p < NT; p++) {
        int j0 = p * 32;

        // local redundant diag factor
        for (int l = tid; l < 1024; l += NTHR)
            Dg[(l >> 5) * 33 + (l & 31)] = g_C[(size_t)(j0 + (l >> 5)) * Dn + j0 + (l & 31)];
        __syncthreads();
        if (tid < 32) {
            factor32_warp(Dg, tid);
            sDinv[tid] = 1.0f / Dg[tid * 33 + tid];
        }
        __syncthreads();

        // block 0 writes diag L
        if (bid == 0) {
            for (int l = tid; l < 1024; l += NTHR) {
                int ii = l >> 5, kk = l & 31;
                if (kk <= ii) g_L[(size_t)(j0 + ii) * Dn + j0 + kk] = Dg[ii * 33 + kk];
            }
        }

        int m = NT - 1 - p;                    // trailing strips
        int ntile = m * (m + 1) / 2;
        if (bid < ntile) {
            int ti = 0;
            while ((ti + 1) * (ti + 2) / 2 <= bid) ti++;
            int tj = bid - ti * (ti + 1) / 2;
            int i0 = (p + 1 + ti) * 32;
            int k0 = (p + 1 + tj) * 32;
            bool diag = (ti == tj);

            // stage raw strips
            for (int l = tid; l < 1024; l += NTHR) {
                int rr = l >> 5, cc = l & 31;
                Pi[rr * 33 + cc] = g_C[(size_t)(i0 + rr) * Dn + j0 + cc];
                if (!diag)
                    Pk[rr * 33 + cc] = g_C[(size_t)(k0 + rr) * Dn + j0 + cc];
            }
            __syncthreads();

            // local TRSM (rank-1 forward substitution), rows 0..63
            int nrows = diag ? 32 : 64;
            if (tid < nrows) {
                float* S = (tid < 32) ? Pi : Pk;
                int rr = tid & 31;
                float t[32];
#pragma unroll
                for (int j = 0; j < 32; j++) t[j] = S[rr * 33 + j];
#pragma unroll
                for (int j = 0; j < 32; j++) {
                    t[j] *= sDinv[j];
                    float tj_ = t[j];
#pragma unroll
                    for (int k2 = 0; k2 < 32; k2++)
                        if (k2 > j) t[k2] -= tj_ * Dg[k2 * 33 + j];
                }
#pragma unroll
                for (int j = 0; j < 32; j++) S[rr * 33 + j] = t[j];
            }
            __syncthreads();

            // (i,i) block publishes strip i of L
            if (diag) {
                for (int l = tid; l < 1024; l += NTHR) {
                    int rr = l >> 5, cc = l & 31;
                    g_L[(size_t)(i0 + rr) * Dn + j0 + cc] = Pi[rr * 33 + cc];
                }
            }

            // SYRK: g_C(i,k) -= Pi * Pk^T
            const float* PK = diag ? Pi : Pk;
            int r  = tid >> 3;
            int cb = (tid & 7) * 4;
            float acc[4] = {0.f, 0.f, 0.f, 0.f};
#pragma unroll 8
            for (int mm = 0; mm < 32; mm++) {
                float a = Pi[r * 33 + mm];
#pragma unroll
                for (int c = 0; c < 4; c++) acc[c] += a * PK[(cb + c) * 33 + mm];
            }
#pragma unroll
            for (int c = 0; c < 4; c++) {
                size_t gi = (size_t)(i0 + r) * Dn + k0 + cb + c;
                g_C[gi] -= acc[c];
            }
        }
        gbar(&phase);
    }

    // ---- output: warp per d. gmean computed from g_pmean via shfl-reduce ---
    {
        int lane = tid & 31;
        int d    = bid * 8 + (tid >> 5);
        if (d < Dn) {
            float gs = 0.f;
#pragma unroll
            for (int q = 0; q < 8; q++) {
                int pr = lane * 8 + q;
                gs += g_pmean[pr >> 5][pr & 31][d];
            }
#pragma unroll
            for (int off = 16; off > 0; off >>= 1)
                gs += __shfl_xor_sync(0xffffffffu, gs, off);
            float acc = gs * (1.0f / ((float)Tn * (float)Bn));
            const float* Lrow = g_L + (size_t)d * Dn;
            float a0 = 0.f, a1 = 0.f, a2 = 0.f, a3 = 0.f;
            int e = 0;
            for (; e + 3 <= d; e += 4) {
                a0 += g_zT[(e + 0) * ZB + lane] * Lrow[e + 0];
                a1 += g_zT[(e + 1) * ZB + lane] * Lrow[e + 1];
                a2 += g_zT[(e + 2) * ZB + lane] * Lrow[e + 2];
                a3 += g_zT[(e + 3) * ZB + lane] * Lrow[e + 3];
            }
            for (; e <= d; e++) a0 += g_zT[e * ZB + lane] * Lrow[e];
            acc += (a0 + a1) + (a2 + a3);
            out[(size_t)lane * Dn + d] = acc;
        }
    }
}

// ---------------- launch -----------------------------------------------------
extern "C" void kernel_launch(void* const* d_in, const int* in_sizes, int n_in,
                              void* d_out, int out_size) {
    const float* x = (const float*)d_in[0];
    const float* z = (const float*)d_in[1];
    if (in_sizes[0] != Bn * Tn * Dn) { x = (const float*)d_in[1]; z = (const float*)d_in[0]; }
    float* out = (float*)d_out;

    conv_mean<<<dim3(4, Bn, SEG), 128>>>(x);

    __nv_bfloat16* xcb;
    cudaGetSymbolAddress((void**)&xcb, g_xcb);
    gram_mma<<<dim3(4, 4, SPLIT), 256>>>(xcb);

    chol_fast<<<NBLK, NTHR>>>(z, out);
}

// round 13
// speedup vs baseline: 2.8201x; 1.7876x over previous
#include <cuda_runtime.h>
#include <cuda_bf16.h>
#include <cstdint>
#include <math.h>

#define Bn 32
#define Tn 2048
#define Dn 512
#define ZB 32
#define SPLIT 32
#define SEG 8
#define NIT (Tn / 32)

#define NT 16
#define NTILE (NT * (NT + 1) / 2)   // 136 lower cov tiles
#define NBLK 120
#define NTHR 256

// ---------------- static scratch ----------------
__device__ float g_pmean[SEG][Bn][Dn];
__device__ float g_zT[Dn * ZB];                 // z transposed [e][s]
__device__ __nv_bfloat16 g_xcb[(size_t)Bn * Tn * Dn];
__device__ float g_Gpart[SPLIT][Dn * Dn];
__device__ float g_C[Dn * Dn];                  // raw updated covariance (lower tiles)
__device__ float g_L[Dn * Dn];                  // Cholesky factor L (lower)
__device__ unsigned g_barrier;

__device__ __forceinline__ uint32_t smem_u32(const void* p) {
    return (uint32_t)__cvta_generic_to_shared(p);
}

// grid barrier: release-add, relaxed spin, single acquire fence
__device__ __forceinline__ void gbar(unsigned* phase) {
    __syncthreads();
    if (threadIdx.x == 0) {
        unsigned target = (++(*phase)) * NBLK;
        asm volatile("red.release.gpu.add.u32 [%0], 1;" :: "l"(&g_barrier) : "memory");
        unsigned v;
        do {
            asm volatile("ld.relaxed.gpu.u32 %0, [%1];" : "=r"(v) : "l"(&g_barrier) : "memory");
        } while (v < target);
        asm volatile("fence.acq_rel.gpu;" ::: "memory");
    }
    __syncthreads();
}

// ---------------- 1) fused partial means + bf16 convert (float2) ------------
__global__ void conv_mean(const float* __restrict__ x) {
    int b   = blockIdx.y;
    int seg = blockIdx.z;
    int tid = threadIdx.x;                    // 128
    int d0  = blockIdx.x * 256 + tid * 2;
    if (blockIdx.x == 0 && b == 0 && seg == 0 && tid == 0) g_barrier = 0u;
    size_t base = ((size_t)b * Tn + (size_t)seg * (Tn / SEG)) * Dn + d0;
    float s0 = 0.f, s1 = 0.f;
#pragma unroll 8
    for (int t = 0; t < Tn / SEG; t++) {
        float2 v = *(const float2*)(x + base + (size_t)t * Dn);
        s0 += v.x; s1 += v.y;
        __nv_bfloat162 h;
        h.x = __float2bfloat16_rn(v.x);
        h.y = __float2bfloat16_rn(v.y);
        *(__nv_bfloat162*)(g_xcb + base + (size_t)t * Dn) = h;
    }
    g_pmean[seg][b][d0]     = s0;
    g_pmean[seg][b][d0 + 1] = s1;
}

// ---------------- 2) tensor-core Gram (validated, unchanged) ----------------
__global__ void __launch_bounds__(256) gram_mma(const __nv_bfloat16* __restrict__ xb) {
    if (blockIdx.y > blockIdx.x) return;
    int dtile = blockIdx.x * 128;
    int etile = blockIdx.y * 128;
    int bz    = blockIdx.z;

    __shared__ __nv_bfloat16 As[2][32][128];
    __shared__ __nv_bfloat16 Bs[2][32][128];

    int tid  = threadIdx.x;
    int lane = tid & 31;
    int warp = tid >> 5;
    int m0 = (warp >> 2) * 64;
    int n0 = (warp & 3) * 32;

    const __nv_bfloat16* xbase = xb + (size_t)bz * Tn * Dn;

    float acc[4][4][4];
#pragma unroll
    for (int a = 0; a < 4; a++)
#pragma unroll
        for (int b = 0; b < 4; b++)
#pragma unroll
            for (int c = 0; c < 4; c++) acc[a][b][c] = 0.f;

    auto issue = [&](int it, int stg) {
#pragma unroll
        for (int rep = 0; rep < 2; rep++) {
            int l    = tid + rep * 256;
            int row  = l >> 4;
            int ch   = l & 15;
            int chs  = ch ^ (row & 7);
            const __nv_bfloat16* gA = xbase + (size_t)(it * 32 + row) * Dn + dtile + ch * 8;
            const __nv_bfloat16* gB = xbase + (size_t)(it * 32 + row) * Dn + etile + ch * 8;
            uint32_t sA = smem_u32(&As[stg][row][chs * 8]);
            uint32_t sB = smem_u32(&Bs[stg][row][chs * 8]);
            asm volatile("cp.async.cg.shared.global [%0], [%1], 16;" :: "r"(sA), "l"(gA));
            asm volatile("cp.async.cg.shared.global [%0], [%1], 16;" :: "r"(sB), "l"(gB));
        }
    };

    issue(0, 0);
    asm volatile("cp.async.commit_group;");

    for (int it = 0; it < NIT; it++) {
        if (it + 1 < NIT) {
            issue(it + 1, (it + 1) & 1);
            asm volatile("cp.async.commit_group;");
            asm volatile("cp.async.wait_group 1;");
        } else {
            asm volatile("cp.async.wait_group 0;");
        }
        __syncthreads();
        int stg = it & 1;

#pragma unroll
        for (int ks = 0; ks < 2; ks++) {
            uint32_t a[4][4];
            uint32_t bfr[2][4];
#pragma unroll
            for (int mi = 0; mi < 4; mi++) {
                int krow = ks * 16 + (lane & 7) + ((lane & 16) ? 8 : 0);
                int ch   = (m0 >> 3) + mi * 2 + ((lane >> 3) & 1);
                int chs  = ch ^ (krow & 7);
                uint32_t addr = smem_u32(&As[stg][krow][chs * 8]);
                asm volatile("ldmatrix.sync.aligned.m8n8.x4.trans.shared.b16 {%0,%1,%2,%3}, [%4];"
                             : "=r"(a[mi][0]), "=r"(a[mi][1]), "=r"(a[mi][2]), "=r"(a[mi][3])
                             : "r"(addr));
            }
#pragma unroll
            for (int pb = 0; pb < 2; pb++) {
                int krow = ks * 16 + (lane & 7) + ((lane & 8) ? 8 : 0);
                int ch   = (n0 >> 3) + pb * 2 + ((lane >> 4) & 1);
                int chs  = ch ^ (krow & 7);
                uint32_t addr = smem_u32(&Bs[stg][krow][chs * 8]);
                asm volatile("ldmatrix.sync.aligned.m8n8.x4.trans.shared.b16 {%0,%1,%2,%3}, [%4];"
                             : "=r"(bfr[pb][0]), "=r"(bfr[pb][1]), "=r"(bfr[pb][2]), "=r"(bfr[pb][3])
                             : "r"(addr));
            }
#pragma unroll
            for (int mi = 0; mi < 4; mi++)
#pragma unroll
                for (int nb = 0; nb < 4; nb++) {
                    uint32_t b0 = bfr[nb >> 1][(nb & 1) * 2];
                    uint32_t b1 = bfr[nb >> 1][(nb & 1) * 2 + 1];
                    asm volatile(
                        "mma.sync.aligned.m16n8k16.row.col.f32.bf16.bf16.f32 "
                        "{%0,%1,%2,%3}, {%4,%5,%6,%7}, {%8,%9}, {%0,%1,%2,%3};"
                        : "+f"(acc[mi][nb][0]), "+f"(acc[mi][nb][1]),
                          "+f"(acc[mi][nb][2]), "+f"(acc[mi][nb][3])
                        : "r"(a[mi][0]), "r"(a[mi][1]), "r"(a[mi][2]), "r"(a[mi][3]),
                          "r"(b0), "r"(b1));
                }
        }
        __syncthreads();
    }

    float* gp = g_Gpart[bz];
    int g  = lane >> 2;
    int tg = lane & 3;
#pragma unroll
    for (int mi = 0; mi < 4; mi++)
#pragma unroll
        for (int nb = 0; nb < 4; nb++) {
            int row = dtile + m0 + mi * 16 + g;
            int col = etile + n0 + nb * 8 + tg * 2;
            *(float2*)&gp[(size_t)row * Dn + col]       = make_float2(acc[mi][nb][0], acc[mi][nb][1]);
            *(float2*)&gp[(size_t)(row + 8) * Dn + col] = make_float2(acc[mi][nb][2], acc[mi][nb][3]);
        }
}

// ---------------- warp-shuffle 32x32 Cholesky factor (triangular) -----------
__device__ __forceinline__ void factor32_warp(float* s, int lane) {
    float a[32];
#pragma unroll
    for (int i = 0; i < 32; i++) a[i] = (i >= lane) ? s[i * 33 + lane] : 0.f;
#pragma unroll
    for (int j = 0; j < 32; j++) {
        float pivot = __shfl_sync(0xffffffffu, a[j], j);
        float rinv  = rsqrtf(pivot);
        float lej = 0.f;
#pragma unroll
        for (int i = j; i < 32; i++) {
            float lij = __shfl_sync(0xffffffffu, a[i], j) * rinv;
            if (i == lane) lej = lij;
            if (lane == j) a[i] = lij;
            else if (lane > j && i >= lane) a[i] -= lij * lej;
        }
    }
#pragma unroll
    for (int i = 0; i < 32; i++)
        if (i >= lane) s[i * 33 + lane] = a[i];
}

// ---------------- 3) persistent chol: 1 barrier per panel -------------------
__global__ void __launch_bounds__(NTHR) chol_fast(const float* __restrict__ z,
                                                  float* __restrict__ out) {
    __shared__ float Pi[32 * 33];
    __shared__ float Pk[32 * 33];
    __shared__ float Dg[32 * 33];
    __shared__ float sDinv[32];

    unsigned phase = 0;
    int bid = blockIdx.x, tid = threadIdx.x;

    // ---- phase A: z transpose + cov lower tiles (bmean from g_pmean) ----
    for (int idx = bid * NTHR + tid; idx < ZB * Dn; idx += NBLK * NTHR) {
        int s = idx >> 9, e = idx & 511;
        g_zT[e * ZB + s] = z[idx];
    }
    {
        const float inv   = 1.0f / ((float)(Tn - 1) * (float)Bn);
        const float tninv = 1.0f / (float)Tn;
        int r  = tid >> 3;
        int cb = (tid & 7) * 4;
        for (int t = bid; t < NTILE; t += NBLK) {
            int ti = 0;
            while ((ti + 1) * (ti + 2) / 2 <= t) ti++;
            int tj = t - ti * (ti + 1) / 2;
            __syncthreads();
            for (int l = tid; l < Bn * 32; l += NTHR) {
                int b = l >> 5, rr = l & 31;
                float s1 = 0.f, s2 = 0.f;
#pragma unroll
                for (int sg = 0; sg < SEG; sg++) {
                    s1 += g_pmean[sg][b][ti * 32 + rr];
                    s2 += g_pmean[sg][b][tj * 32 + rr];
                }
                Pi[b * 33 + rr] = s1 * tninv;
                Pk[b * 33 + rr] = s2 * tninv;
            }
            __syncthreads();
            float4 gs = make_float4(0.f, 0.f, 0.f, 0.f);
            size_t gidx = (size_t)(ti * 32 + r) * Dn + tj * 32 + cb;
#pragma unroll
            for (int g = 0; g < SPLIT; g++) {
                float4 v = *(const float4*)&g_Gpart[g][gidx];
                gs.x += v.x; gs.y += v.y; gs.z += v.z; gs.w += v.w;
            }
            float mk[4] = {0.f, 0.f, 0.f, 0.f};
#pragma unroll
            for (int b = 0; b < Bn; b++) {
                float pir = Pi[b * 33 + r];
#pragma unroll
                for (int c = 0; c < 4; c++) mk[c] += pir * Pk[b * 33 + cb + c];
            }
            float4 res;
            res.x = (gs.x - (float)Tn * mk[0]) * inv;
            res.y = (gs.y - (float)Tn * mk[1]) * inv;
            res.z = (gs.z - (float)Tn * mk[2]) * inv;
            res.w = (gs.w - (float)Tn * mk[3]) * inv;
            *(float4*)&g_C[gidx] = res;
        }
    }
    gbar(&phase);

    // ---- panels: each block factors diag locally; one barrier per panel ----
    int rT = tid >> 3;            // 0..31 (row for float4 ops)
    int cT = (tid & 7) * 4;       // col*4
    for (int p = 0; p < NT; p++) {
        int j0 = p * 32;
        int m = NT - 1 - p;
        int ntile = m * (m + 1) / 2;

        if (bid < ntile || bid == 0) {
            // diag load (1 LDG.128 per thread) + local factor
            {
                float4 v = *(const float4*)&g_C[(size_t)(j0 + rT) * Dn + j0 + cT];
                Dg[rT * 33 + cT]     = v.x;
                Dg[rT * 33 + cT + 1] = v.y;
                Dg[rT * 33 + cT + 2] = v.z;
                Dg[rT * 33 + cT + 3] = v.w;
            }
            __syncthreads();
            if (tid < 32) {
                factor32_warp(Dg, tid);
                sDinv[tid] = 1.0f / Dg[tid * 33 + tid];
            }
            __syncthreads();

            // block 0 writes diag L
            if (bid == 0) {
                for (int l = tid; l < 1024; l += NTHR) {
                    int ii = l >> 5, kk = l & 31;
                    if (kk <= ii) g_L[(size_t)(j0 + ii) * Dn + j0 + kk] = Dg[ii * 33 + kk];
                }
            }

            if (bid < ntile) {
                int ti = 0;
                while ((ti + 1) * (ti + 2) / 2 <= bid) ti++;
                int tj = bid - ti * (ti + 1) / 2;
                int i0 = (p + 1 + ti) * 32;
                int k0 = (p + 1 + tj) * 32;
                bool diag = (ti == tj);

                // stage raw strips (float4)
                {
                    float4 v = *(const float4*)&g_C[(size_t)(i0 + rT) * Dn + j0 + cT];
                    Pi[rT * 33 + cT]     = v.x;
                    Pi[rT * 33 + cT + 1] = v.y;
                    Pi[rT * 33 + cT + 2] = v.z;
                    Pi[rT * 33 + cT + 3] = v.w;
                    if (!diag) {
                        float4 w = *(const float4*)&g_C[(size_t)(k0 + rT) * Dn + j0 + cT];
                        Pk[rT * 33 + cT]     = w.x;
                        Pk[rT * 33 + cT + 1] = w.y;
                        Pk[rT * 33 + cT + 2] = w.z;
                        Pk[rT * 33 + cT + 3] = w.w;
                    }
                }
                __syncthreads();

                // local TRSM (triangular forward substitution), rows 0..63
                int nrows = diag ? 32 : 64;
                if (tid < nrows) {
                    float* S = (tid < 32) ? Pi : Pk;
                    int rr = tid & 31;
                    float t[32];
#pragma unroll
                    for (int j = 0; j < 32; j++) t[j] = S[rr * 33 + j];
#pragma unroll
                    for (int j = 0; j < 32; j++) {
                        float tj_ = t[j] * sDinv[j];
                        t[j] = tj_;
#pragma unroll
                        for (int k2 = j + 1; k2 < 32; k2++)
                            t[k2] -= tj_ * Dg[k2 * 33 + j];
                    }
#pragma unroll
                    for (int j = 0; j < 32; j++) S[rr * 33 + j] = t[j];
                }
                __syncthreads();

                // (i,i) block publishes strip i of L
                if (diag) {
                    for (int l = tid; l < 1024; l += NTHR) {
                        int rr = l >> 5, cc = l & 31;
                        g_L[(size_t)(i0 + rr) * Dn + j0 + cc] = Pi[rr * 33 + cc];
                    }
                }

                // SYRK: g_C(i,k) -= Pi * Pk^T (full square, float4 RMW)
                const float* PK = diag ? Pi : Pk;
                float acc[4] = {0.f, 0.f, 0.f, 0.f};
#pragma unroll 8
                for (int mm = 0; mm < 32; mm++) {
                    float a = Pi[rT * 33 + mm];
#pragma unroll
                    for (int c = 0; c < 4; c++) acc[c] += a * PK[(cT + c) * 33 + mm];
                }
                {
                    float4 cv = *(const float4*)&g_C[(size_t)(i0 + rT) * Dn + k0 + cT];
                    cv.x -= acc[0]; cv.y -= acc[1]; cv.z -= acc[2]; cv.w -= acc[3];
                    *(float4*)&g_C[(size_t)(i0 + rT) * Dn + k0 + cT] = cv;
                }
            }
        }
        gbar(&phase);
    }

    // ---- output: warp per d. gmean computed from g_pmean via shfl-reduce ---
    {
        int lane = tid & 31;
        int d    = bid * 8 + (tid >> 5);
        if (d < Dn) {
            float gs = 0.f;
#pragma unroll
            for (int q = 0; q < 8; q++) {
                int pr = lane * 8 + q;
                gs += g_pmean[pr >> 5][pr & 31][d];
            }
#pragma unroll
            for (int off = 16; off > 0; off >>= 1)
                gs += __shfl_xor_sync(0xffffffffu, gs, off);
            float acc = gs * (1.0f / ((float)Tn * (float)Bn));
            const float* Lrow = g_L + (size_t)d * Dn;
            float a0 = 0.f, a1 = 0.f, a2 = 0.f, a3 = 0.f;
            int e = 0;
            for (; e + 3 <= d; e += 4) {
                a0 += g_zT[(e + 0) * ZB + lane] * Lrow[e + 0];
                a1 += g_zT[(e + 1) * ZB + lane] * Lrow[e + 1];
                a2 += g_zT[(e + 2) * ZB + lane] * Lrow[e + 2];
                a3 += g_zT[(e + 3) * ZB + lane] * Lrow[e + 3];
            }
            for (; e <= d; e++) a0 += g_zT[e * ZB + lane] * Lrow[e];
            acc += (a0 + a1) + (a2 + a3);
            out[(size_t)lane * Dn + d] = acc;
        }
    }
}

// ---------------- launch -----------------------------------------------------
extern "C" void kernel_launch(void* const* d_in, const int* in_sizes, int n_in,
                              void* d_out, int out_size) {
    const float* x = (const float*)d_in[0];
    const float* z = (const float*)d_in[1];
    if (in_sizes[0] != Bn * Tn * Dn) { x = (const float*)d_in[1]; z = (const float*)d_in[0]; }
    float* out = (float*)d_out;

    conv_mean<<<dim3(2, Bn, SEG), 128>>>(x);

    __nv_bfloat16* xcb;
    cudaGetSymbolAddress((void**)&xcb, g_xcb);
    gram_mma<<<dim3(4, 4, SPLIT), 256>>>(xcb);

    chol_fast<<<NBLK, NTHR>>>(z, out);
}

// round 14
// speedup vs baseline: 2.8362x; 1.0057x over previous
#include <cuda_runtime.h>
#include <cuda_bf16.h>
#include <cstdint>
#include <math.h>

#define Bn 32
#define Tn 2048
#define Dn 512
#define ZB 32
#define SPLIT 32
#define SEG 16
#define NIT (Tn / 32)

#define NT 16
#define NTILE (NT * (NT + 1) / 2)   // 136 lower cov tiles
#define NBLK 120
#define NTHR 256
#define GTILE 10                    // lower 128x128 tiles of 4x4

// ---------------- static scratch ----------------
__device__ float g_pmean[SEG][Bn][Dn];
__device__ float g_zT[Dn * ZB];                 // z transposed [e][s]
__device__ __nv_bfloat16 g_xcb[(size_t)Bn * Tn * Dn];
__device__ float g_Gpart[SPLIT][Dn * Dn];
__device__ float g_C[Dn * Dn];                  // raw updated covariance (lower tiles)
__device__ float g_L[Dn * Dn];                  // Cholesky factor L (lower)
__device__ unsigned g_bar8[8 * 32];             // distributed barrier counters (128B apart)

__device__ __forceinline__ uint32_t smem_u32(const void* p) {
    return (uint32_t)__cvta_generic_to_shared(p);
}

// grid barrier: distributed arrival (8 lines), relaxed poll, single acquire fence
__device__ __forceinline__ void gbar(unsigned* phase) {
    __syncthreads();
    if (threadIdx.x == 0) {
        unsigned target = (++(*phase)) * NBLK;
        asm volatile("red.release.gpu.add.u32 [%0], 1;"
                     :: "l"(&g_bar8[(blockIdx.x & 7) * 32]) : "memory");
        unsigned s;
        do {
            s = 0;
#pragma unroll
            for (int c = 0; c < 8; c++) {
                unsigned v;
                asm volatile("ld.relaxed.gpu.u32 %0, [%1];"
                             : "=r"(v) : "l"(&g_bar8[c * 32]) : "memory");
                s += v;
            }
        } while (s < target);
        asm volatile("fence.acq_rel.gpu;" ::: "memory");
    }
    __syncthreads();
}

// ---------------- 1) fused partial means + bf16 convert (float4) ------------
__global__ void conv_mean(const float* __restrict__ x) {
    int b   = blockIdx.y;
    int seg = blockIdx.z;
    int tid = threadIdx.x;                    // 128
    int d0  = tid * 4;                        // 128*4 = 512
    if (b == 0 && seg == 0 && tid < 8) g_bar8[tid * 32] = 0u;
    size_t base = ((size_t)b * Tn + (size_t)seg * (Tn / SEG)) * Dn + d0;
    float s0 = 0.f, s1 = 0.f, s2 = 0.f, s3 = 0.f;
#pragma unroll 8
    for (int t = 0; t < Tn / SEG; t++) {
        float4 v = *(const float4*)(x + base + (size_t)t * Dn);
        s0 += v.x; s1 += v.y; s2 += v.z; s3 += v.w;
        __nv_bfloat162 h0, h1;
        h0.x = __float2bfloat16_rn(v.x);
        h0.y = __float2bfloat16_rn(v.y);
        h1.x = __float2bfloat16_rn(v.z);
        h1.y = __float2bfloat16_rn(v.w);
        uint2 packed;
        packed.x = *(uint32_t*)&h0;
        packed.y = *(uint32_t*)&h1;
        *(uint2*)(g_xcb + base + (size_t)t * Dn) = packed;
    }
    g_pmean[seg][b][d0]     = s0;
    g_pmean[seg][b][d0 + 1] = s1;
    g_pmean[seg][b][d0 + 2] = s2;
    g_pmean[seg][b][d0 + 3] = s3;
}

// ---------------- 2) tensor-core Gram: flattened grid, 3-stage pipeline -----
__global__ void __launch_bounds__(256) gram_mma(const __nv_bfloat16* __restrict__ xb) {
    // flatten: 320 blocks = 10 lower tiles x 32 batches
    int t  = blockIdx.x / SPLIT;
    int bz = blockIdx.x - t * SPLIT;
    int ti = 0;
    while ((ti + 1) * (ti + 2) / 2 <= t) ti++;
    int tj = t - ti * (ti + 1) / 2;
    int dtile = ti * 128;
    int etile = tj * 128;

    __shared__ __nv_bfloat16 As[3][32][128];
    __shared__ __nv_bfloat16 Bs[3][32][128];

    int tid  = threadIdx.x;
    int lane = tid & 31;
    int warp = tid >> 5;
    int m0 = (warp >> 2) * 64;
    int n0 = (warp & 3) * 32;

    const __nv_bfloat16* xbase = xb + (size_t)bz * Tn * Dn;

    float acc[4][4][4];
#pragma unroll
    for (int a = 0; a < 4; a++)
#pragma unroll
        for (int b = 0; b < 4; b++)
#pragma unroll
            for (int c = 0; c < 4; c++) acc[a][b][c] = 0.f;

    auto issue = [&](int it, int stg) {
#pragma unroll
        for (int rep = 0; rep < 2; rep++) {
            int l    = tid + rep * 256;
            int row  = l >> 4;
            int ch   = l & 15;
            int chs  = ch ^ (row & 7);
            const __nv_bfloat16* gA = xbase + (size_t)(it * 32 + row) * Dn + dtile + ch * 8;
            const __nv_bfloat16* gB = xbase + (size_t)(it * 32 + row) * Dn + etile + ch * 8;
            uint32_t sA = smem_u32(&As[stg][row][chs * 8]);
            uint32_t sB = smem_u32(&Bs[stg][row][chs * 8]);
            asm volatile("cp.async.cg.shared.global [%0], [%1], 16;" :: "r"(sA), "l"(gA));
            asm volatile("cp.async.cg.shared.global [%0], [%1], 16;" :: "r"(sB), "l"(gB));
        }
    };

    issue(0, 0);
    asm volatile("cp.async.commit_group;");
    issue(1, 1);
    asm volatile("cp.async.commit_group;");

    int stg = 0;
    for (int it = 0; it < NIT; it++) {
        if (it + 2 < NIT) {
            issue(it + 2, (it + 2) % 3);
            asm volatile("cp.async.commit_group;");
            asm volatile("cp.async.wait_group 2;");
        } else if (it + 1 < NIT) {
            asm volatile("cp.async.wait_group 1;");
        } else {
            asm volatile("cp.async.wait_group 0;");
        }
        __syncthreads();

#pragma unroll
        for (int ks = 0; ks < 2; ks++) {
            uint32_t a[4][4];
            uint32_t bfr[2][4];
#pragma unroll
            for (int mi = 0; mi < 4; mi++) {
                int krow = ks * 16 + (lane & 7) + ((lane & 16) ? 8 : 0);
                int ch   = (m0 >> 3) + mi * 2 + ((lane >> 3) & 1);
                int chs  = ch ^ (krow & 7);
                uint32_t addr = smem_u32(&As[stg][krow][chs * 8]);
                asm volatile("ldmatrix.sync.aligned.m8n8.x4.trans.shared.b16 {%0,%1,%2,%3}, [%4];"
                             : "=r"(a[mi][0]), "=r"(a[mi][1]), "=r"(a[mi][2]), "=r"(a[mi][3])
                             : "r"(addr));
            }
#pragma unroll
            for (int pb = 0; pb < 2; pb++) {
                int krow = ks * 16 + (lane & 7) + ((lane & 8) ? 8 : 0);
                int ch   = (n0 >> 3) + pb * 2 + ((lane >> 4) & 1);
                int chs  = ch ^ (krow & 7);
                uint32_t addr = smem_u32(&Bs[stg][krow][chs * 8]);
                asm volatile("ldmatrix.sync.aligned.m8n8.x4.trans.shared.b16 {%0,%1,%2,%3}, [%4];"
                             : "=r"(bfr[pb][0]), "=r"(bfr[pb][1]), "=r"(bfr[pb][2]), "=r"(bfr[pb][3])
                             : "r"(addr));
            }
#pragma unroll
            for (int mi = 0; mi < 4; mi++)
#pragma unroll
                for (int nb = 0; nb < 4; nb++) {
                    uint32_t b0 = bfr[nb >> 1][(nb & 1) * 2];
                    uint32_t b1 = bfr[nb >> 1][(nb & 1) * 2 + 1];
                    asm volatile(
                        "mma.sync.aligned.m16n8k16.row.col.f32.bf16.bf16.f32 "
                        "{%0,%1,%2,%3}, {%4,%5,%6,%7}, {%8,%9}, {%0,%1,%2,%3};"
                        : "+f"(acc[mi][nb][0]), "+f"(acc[mi][nb][1]),
                          "+f"(acc[mi][nb][2]), "+f"(acc[mi][nb][3])
                        : "r"(a[mi][0]), "r"(a[mi][1]), "r"(a[mi][2]), "r"(a[mi][3]),
                          "r"(b0), "r"(b1));
                }
        }
        __syncthreads();
        stg = (stg + 1 == 3) ? 0 : stg + 1;
    }

    float* gp = g_Gpart[bz];
    int g  = lane >> 2;
    int tg = lane & 3;
#pragma unroll
    for (int mi = 0; mi < 4; mi++)
#pragma unroll
        for (int nb = 0; nb < 4; nb++) {
            int row = dtile + m0 + mi * 16 + g;
            int col = etile + n0 + nb * 8 + tg * 2;
            *(float2*)&gp[(size_t)row * Dn + col]       = make_float2(acc[mi][nb][0], acc[mi][nb][1]);
            *(float2*)&gp[(size_t)(row + 8) * Dn + col] = make_float2(acc[mi][nb][2], acc[mi][nb][3]);
        }
}

// ---------------- warp-shuffle 32x32 Cholesky factor (triangular) -----------
__device__ __forceinline__ void factor32_warp(float* s, int lane) {
    float a[32];
#pragma unroll
    for (int i = 0; i < 32; i++) a[i] = (i >= lane) ? s[i * 33 + lane] : 0.f;
#pragma unroll
    for (int j = 0; j < 32; j++) {
        float pivot = __shfl_sync(0xffffffffu, a[j], j);
        float rinv  = rsqrtf(pivot);
        float lej = 0.f;
#pragma unroll
        for (int i = j; i < 32; i++) {
            float lij = __shfl_sync(0xffffffffu, a[i], j) * rinv;
            if (i == lane) lej = lij;
            if (lane == j) a[i] = lij;
            else if (lane > j && i >= lane) a[i] -= lij * lej;
        }
    }
#pragma unroll
    for (int i = 0; i < 32; i++)
        if (i >= lane) s[i * 33 + lane] = a[i];
}

// ---------------- 3) persistent chol: 1 barrier per panel -------------------
__global__ void __launch_bounds__(NTHR) chol_fast(const float* __restrict__ z,
                                                  float* __restrict__ out) {
    __shared__ float Pi[32 * 33];
    __shared__ float Pk[32 * 33];
    __shared__ float Dg[32 * 33];
    __shared__ float sDinv[32];

    unsigned phase = 0;
    int bid = blockIdx.x, tid = threadIdx.x;

    // ---- phase A: z transpose + cov lower tiles (bmean from g_pmean) ----
    for (int idx = bid * NTHR + tid; idx < ZB * Dn; idx += NBLK * NTHR) {
        int s = idx >> 9, e = idx & 511;
        g_zT[e * ZB + s] = z[idx];
    }
    {
        const float inv   = 1.0f / ((float)(Tn - 1) * (float)Bn);
        const float tninv = 1.0f / (float)Tn;
        int r  = tid >> 3;
        int cb = (tid & 7) * 4;
        for (int t = bid; t < NTILE; t += NBLK) {
            int ti = 0;
            while ((ti + 1) * (ti + 2) / 2 <= t) ti++;
            int tj = t - ti * (ti + 1) / 2;
            __syncthreads();
            for (int l = tid; l < Bn * 32; l += NTHR) {
                int b = l >> 5, rr = l & 31;
                float s1 = 0.f, s2 = 0.f;
#pragma unroll
                for (int sg = 0; sg < SEG; sg++) {
                    s1 += g_pmean[sg][b][ti * 32 + rr];
                    s2 += g_pmean[sg][b][tj * 32 + rr];
                }
                Pi[b * 33 + rr] = s1 * tninv;
                Pk[b * 33 + rr] = s2 * tninv;
            }
            __syncthreads();
            float4 gs = make_float4(0.f, 0.f, 0.f, 0.f);
            size_t gidx = (size_t)(ti * 32 + r) * Dn + tj * 32 + cb;
#pragma unroll
            for (int g = 0; g < SPLIT; g++) {
                float4 v = *(const float4*)&g_Gpart[g][gidx];
                gs.x += v.x; gs.y += v.y; gs.z += v.z; gs.w += v.w;
            }
            float mk[4] = {0.f, 0.f, 0.f, 0.f};
#pragma unroll
            for (int b = 0; b < Bn; b++) {
                float pir = Pi[b * 33 + r];
#pragma unroll
                for (int c = 0; c < 4; c++) mk[c] += pir * Pk[b * 33 + cb + c];
            }
            float4 res;
            res.x = (gs.x - (float)Tn * mk[0]) * inv;
            res.y = (gs.y - (float)Tn * mk[1]) * inv;
            res.z = (gs.z - (float)Tn * mk[2]) * inv;
            res.w = (gs.w - (float)Tn * mk[3]) * inv;
            *(float4*)&g_C[gidx] = res;
        }
    }
    gbar(&phase);

    // ---- panels: each block factors diag locally; one barrier per panel ----
    int rT = tid >> 3;            // 0..31 (row for float4 ops)
    int cT = (tid & 7) * 4;       // col*4
    for (int p = 0; p < NT; p++) {
        int j0 = p * 32;
        int m = NT - 1 - p;
        int ntile = m * (m + 1) / 2;

        if (bid < ntile || bid == 0) {
            // diag load (1 LDG.128 per thread) + local factor
            {
                float4 v = *(const float4*)&g_C[(size_t)(j0 + rT) * Dn + j0 + cT];
                Dg[rT * 33 + cT]     = v.x;
                Dg[rT * 33 + cT + 1] = v.y;
                Dg[rT * 33 + cT + 2] = v.z;
                Dg[rT * 33 + cT + 3] = v.w;
            }
            __syncthreads();
            if (tid < 32) {
                factor32_warp(Dg, tid);
                sDinv[tid] = 1.0f / Dg[tid * 33 + tid];
            }
            __syncthreads();

            // block 0 writes diag L
            if (bid == 0) {
                for (int l = tid; l < 1024; l += NTHR) {
                    int ii = l >> 5, kk = l & 31;
                    if (kk <= ii) g_L[(size_t)(j0 + ii) * Dn + j0 + kk] = Dg[ii * 33 + kk];
                }
            }

            if (bid < ntile) {
                int ti = 0;
                while ((ti + 1) * (ti + 2) / 2 <= bid) ti++;
                int tj = bid - ti * (ti + 1) / 2;
                int i0 = (p + 1 + ti) * 32;
                int k0 = (p + 1 + tj) * 32;
                bool diag = (ti == tj);

                // stage raw strips (float4)
                {
                    float4 v = *(const float4*)&g_C[(size_t)(i0 + rT) * Dn + j0 + cT];
                    Pi[rT * 33 + cT]     = v.x;
                    Pi[rT * 33 + cT + 1] = v.y;
                    Pi[rT * 33 + cT + 2] = v.z;
                    Pi[rT * 33 + cT + 3] = v.w;
                    if (!diag) {
                        float4 w = *(const float4*)&g_C[(size_t)(k0 + rT) * Dn + j0 + cT];
                        Pk[rT * 33 + cT]     = w.x;
                        Pk[rT * 33 + cT + 1] = w.y;
                        Pk[rT * 33 + cT + 2] = w.z;
                        Pk[rT * 33 + cT + 3] = w.w;
                    }
                }
                __syncthreads();

                // local TRSM (triangular forward substitution), rows 0..63
                int nrows = diag ? 32 : 64;
                if (tid < nrows) {
                    float* S = (tid < 32) ? Pi : Pk;
                    int rr = tid & 31;
                    float t[32];
#pragma unroll
                    for (int j = 0; j < 32; j++) t[j] = S[rr * 33 + j];
#pragma unroll
                    for (int j = 0; j < 32; j++) {
                        float tj_ = t[j] * sDinv[j];
                        t[j] = tj_;
#pragma unroll
                        for (int k2 = j + 1; k2 < 32; k2++)
                            t[k2] -= tj_ * Dg[k2 * 33 + j];
                    }
#pragma unroll
                    for (int j = 0; j < 32; j++) S[rr * 33 + j] = t[j];
                }
                __syncthreads();

                // (i,i) block publishes strip i of L
                if (diag) {
                    for (int l = tid; l < 1024; l += NTHR) {
                        int rr = l >> 5, cc = l & 31;
                        g_L[(size_t)(i0 + rr) * Dn + j0 + cc] = Pi[rr * 33 + cc];
                    }
                }

                // SYRK: g_C(i,k) -= Pi * Pk^T (full square, float4 RMW)
                const float* PK = diag ? Pi : Pk;
                float acc[4] = {0.f, 0.f, 0.f, 0.f};
#pragma unroll 8
                for (int mm = 0; mm < 32; mm++) {
                    float a = Pi[rT * 33 + mm];
#pragma unroll
                    for (int c = 0; c < 4; c++) acc[c] += a * PK[(cT + c) * 33 + mm];
                }
                {
                    float4 cv = *(const float4*)&g_C[(size_t)(i0 + rT) * Dn + k0 + cT];
                    cv.x -= acc[0]; cv.y -= acc[1]; cv.z -= acc[2]; cv.w -= acc[3];
                    *(float4*)&g_C[(size_t)(i0 + rT) * Dn + k0 + cT] = cv;
                }
            }
        }
        gbar(&phase);
    }

    // ---- output: warp per d. gmean computed from g_pmean via shfl-reduce ---
    {
        int lane = tid & 31;
        int d    = bid * 8 + (tid >> 5);
        if (d < Dn) {
            float gs = 0.f;
#pragma unroll
            for (int q = 0; q < 16; q++) {
                int pr = lane * 16 + q;
                gs += g_pmean[pr >> 5][pr & 31][d];
            }
#pragma unroll
            for (int off = 16; off > 0; off >>= 1)
                gs += __shfl_xor_sync(0xffffffffu, gs, off);
            float acc = gs * (1.0f / ((float)Tn * (float)Bn));
            const float* Lrow = g_L + (size_t)d * Dn;
            float a0 = 0.f, a1 = 0.f, a2 = 0.f, a3 = 0.f;
            int e = 0;
            for (; e + 3 <= d; e += 4) {
                a0 += g_zT[(e + 0) * ZB + lane] * Lrow[e + 0];
                a1 += g_zT[(e + 1) * ZB + lane] * Lrow[e + 1];
                a2 += g_zT[(e + 2) * ZB + lane] * Lrow[e + 2];
                a3 += g_zT[(e + 3) * ZB + lane] * Lrow[e + 3];
            }
            for (; e <= d; e++) a0 += g_zT[e * ZB + lane] * Lrow[e];
            acc += (a0 + a1) + (a2 + a3);
            out[(size_t)lane * Dn + d] = acc;
        }
    }
}

// ---------------- launch -----------------------------------------------------
extern "C" void kernel_launch(void* const* d_in, const int* in_sizes, int n_in,
                              void* d_out, int out_size) {
    const float* x = (const float*)d_in[0];
    const float* z = (const float*)d_in[1];
    if (in_sizes[0] != Bn * Tn * Dn) { x = (const float*)d_in[1]; z = (const float*)d_in[0]; }
    float* out = (float*)d_out;

    conv_mean<<<dim3(1, Bn, SEG), 128>>>(x);

    __nv_bfloat16* xcb;
    cudaGetSymbolAddress((void**)&xcb, g_xcb);
    gram_mma<<<GTILE * SPLIT, 256>>>(xcb);

    chol_fast<<<NBLK, NTHR>>>(z, out);
}